// round 15
// baseline (speedup 1.0000x reference)
#include <cuda_runtime.h>

#define B_ 64
#define S_ 8192
#define E_ 32
#define H_ 64
#define PT_ 128
#define PTILES_ (S_ / PT_)      // 64
#define TPA_ 4
#define NBA_ (PTILES_ / TPA_)   // 16
#define TPB_ 4
#define NBB_ (PTILES_ / TPB_)   // 16

// strides in 4-byte units (bank patterns carried from R11/R14)
#define QTB_STR 20  // Qt bf16 [f=32][epair=16] u32 (pass A only)
#define W1_STR 20   // W1bf [j=64][epair=16] u32
#define W2_STR 36   // W2bf [e=32][jpair=32] u32

typedef unsigned long long u64;

// q stored as packed (hi,lo) bf16x2 u64, layout [b*S + t][16 pair-cols].
__device__ static u64 g_q2[(size_t)B_ * S_ * 16];
__device__ static float g_part[B_ * NBA_ * E_];

__device__ __forceinline__ float silu_f(float v) {
    return v * __fdividef(1.0f, 1.0f + __expf(-v));
}
__device__ __forceinline__ void mma_bf16(float* d, const unsigned* a,
                                         unsigned b0, unsigned b1) {
    asm("mma.sync.aligned.m16n8k16.row.col.f32.bf16.bf16.f32 "
        "{%0,%1,%2,%3},{%4,%5,%6,%7},{%8,%9},{%0,%1,%2,%3};"
        : "+f"(d[0]), "+f"(d[1]), "+f"(d[2]), "+f"(d[3])
        : "r"(a[0]), "r"(a[1]), "r"(a[2]), "r"(a[3]), "r"(b0), "r"(b1));
}
__device__ __forceinline__ void mma_bf3(float* d, const unsigned* ah, const unsigned* al,
                                        unsigned bh0, unsigned bh1,
                                        unsigned bl0, unsigned bl1) {
    mma_bf16(d, ah, bh0, bh1);
    mma_bf16(d, ah, bl0, bl1);
    mma_bf16(d, al, bh0, bh1);
}
__device__ __forceinline__ unsigned bf2pack(float lo, float hi) {
    unsigned r; asm("cvt.rn.bf16x2.f32 %0, %1, %2;" : "=r"(r) : "f"(hi), "f"(lo));
    return r;
}
__device__ __forceinline__ void bfsplit(float v0, float v1, unsigned& hi, unsigned& lo) {
    hi = bf2pack(v0, v1);
    float h0 = __uint_as_float(hi << 16);
    float h1 = __uint_as_float(hi & 0xFFFF0000u);
    lo = bf2pack(v0 - h0, v1 - h1);
}

// ---------------- Pass A: q = silu(x @ Qw^T); store split-q; sumsq partials ----------
__global__ __launch_bounds__(256) void k_passA(const float* __restrict__ x,
                                               const float* __restrict__ Qw) {
    __shared__ __align__(16) unsigned QtbH[E_ * QTB_STR], QtbL[E_ * QTB_STR];
    __shared__ float ssA[8][E_];
    const int b = blockIdx.y, bx = blockIdx.x, tid = threadIdx.x;
    const int lane = tid & 31, w = tid >> 5;
    const int g = lane >> 2, c = lane & 3;
    const int t0 = w * 16;

    for (int i = tid; i < E_ * (E_ / 2); i += 256) {  // Qw[f][e] -> packed pairs
        int f = i >> 4, ep = i & 15;
        float2 v = *reinterpret_cast<const float2*>(Qw + f * E_ + 2 * ep);
        unsigned hi, lo;
        bfsplit(v.x, v.y, hi, lo);
        QtbH[f * QTB_STR + ep] = hi;
        QtbL[f * QTB_STR + ep] = lo;
    }
    __syncthreads();

    float ss[4][2];
#pragma unroll
    for (int fn = 0; fn < 4; ++fn) ss[fn][0] = ss[fn][1] = 0.f;

    for (int tt = 0; tt < TPA_; ++tt) {
        const int tile = bx * TPA_ + tt;
        const float2* xw2 = reinterpret_cast<const float2*>(
            x + ((size_t)b * S_ + tile * PT_ + t0) * E_);

        float qa[4][4];
#pragma unroll
        for (int fn = 0; fn < 4; ++fn)
#pragma unroll
            for (int i = 0; i < 4; ++i) qa[fn][i] = 0.f;
#pragma unroll
        for (int kc = 0; kc < 2; ++kc) {
            const int p0 = 8 * kc;
            float2 v0 = xw2[g * 16 + p0 + c];
            float2 v1 = xw2[(g + 8) * 16 + p0 + c];
            float2 v2 = xw2[g * 16 + p0 + c + 4];
            float2 v3 = xw2[(g + 8) * 16 + p0 + c + 4];
            unsigned ah[4], al[4];
            bfsplit(v0.x, v0.y, ah[0], al[0]);
            bfsplit(v1.x, v1.y, ah[1], al[1]);
            bfsplit(v2.x, v2.y, ah[2], al[2]);
            bfsplit(v3.x, v3.y, ah[3], al[3]);
            const int k8 = kc * 8;
#pragma unroll
            for (int fn = 0; fn < 4; ++fn) {
                const int fr = fn * 8 + g;
                mma_bf3(qa[fn], ah, al,
                        QtbH[fr * QTB_STR + k8 + c], QtbH[fr * QTB_STR + k8 + c + 4],
                        QtbL[fr * QTB_STR + k8 + c], QtbL[fr * QTB_STR + k8 + c + 4]);
            }
        }

        // silu once; accumulate sumsq; store split-q in A-frag column layout
        u64* q2 = g_q2 + ((size_t)b * S_ + tile * PT_ + t0) * 16;
#pragma unroll
        for (int fn = 0; fn < 4; ++fn) {
            float s0 = silu_f(qa[fn][0]), s1 = silu_f(qa[fn][1]);
            float s2 = silu_f(qa[fn][2]), s3 = silu_f(qa[fn][3]);
            ss[fn][0] += s0 * s0 + s2 * s2;
            ss[fn][1] += s1 * s1 + s3 * s3;
            unsigned h0, l0, h2, l2;
            bfsplit(s0, s1, h0, l0);
            bfsplit(s2, s3, h2, l2);
            q2[g * 16 + fn * 4 + c]       = (u64)h0 | ((u64)l0 << 32);
            q2[(g + 8) * 16 + fn * 4 + c] = (u64)h2 | ((u64)l2 << 32);
        }
    }

#pragma unroll
    for (int m = 4; m <= 16; m <<= 1)
#pragma unroll
        for (int fn = 0; fn < 4; ++fn) {
            ss[fn][0] += __shfl_xor_sync(0xffffffffu, ss[fn][0], m);
            ss[fn][1] += __shfl_xor_sync(0xffffffffu, ss[fn][1], m);
        }
    if (lane < 4) {
#pragma unroll
        for (int fn = 0; fn < 4; ++fn) {
            ssA[w][fn * 8 + 2 * lane]     = ss[fn][0];
            ssA[w][fn * 8 + 2 * lane + 1] = ss[fn][1];
        }
    }
    __syncthreads();
    if (tid < E_) {
        float s = 0.f;
#pragma unroll
        for (int k = 0; k < 8; ++k) s += ssA[k][tid];
        g_part[(b * NBA_ + bx) * E_ + tid] = s;
    }
}

// ---- Pass B: load split-q frags, GEMM1->GEMM2 per-kc register interleave ----
__global__ __launch_bounds__(256) void k_passB(const float* __restrict__ W1,
                                               const float* __restrict__ b1,
                                               const float* __restrict__ W2,
                                               const float* __restrict__ b2,
                                               float* __restrict__ out) {
    __shared__ __align__(16) unsigned w1h[H_ * W1_STR], w1l[H_ * W1_STR];
    __shared__ __align__(16) unsigned w2h[E_ * W2_STR], w2l[E_ * W2_STR];
    __shared__ float b1s[H_], b2s[E_], rsq[E_];

    const int b = blockIdx.y, bx = blockIdx.x, tid = threadIdx.x;
    const int lane = tid & 31, w = tid >> 5;
    const int g = lane >> 2, c = lane & 3;
    const int t0 = w * 16;

    if (tid < E_) {
        float s = 0.f;
#pragma unroll
        for (int k = 0; k < NBA_; ++k) s += g_part[(b * NBA_ + k) * E_ + tid];
        rsq[tid] = 1.0f / fmaxf(sqrtf(s), 1e-12f);
        b2s[tid] = b2[b * E_ + tid];
    }
    if (tid < H_) b1s[tid] = b1[b * H_ + tid];
    __syncthreads();

    const size_t wbase = (size_t)b * H_ * E_;
    for (int i = tid; i < H_ * (E_ / 2); i += 256) {
        int j = i >> 4, ep = i & 15;
        float2 v = *reinterpret_cast<const float2*>(W1 + wbase + j * E_ + 2 * ep);
        unsigned hi, lo;
        bfsplit(v.x * rsq[2 * ep], v.y * rsq[2 * ep + 1], hi, lo);
        w1h[j * W1_STR + ep] = hi;
        w1l[j * W1_STR + ep] = lo;
    }
    for (int i = tid; i < E_ * (H_ / 2); i += 256) {
        int e = i >> 5, jp = i & 31;
        float2 v = *reinterpret_cast<const float2*>(W2 + wbase + e * H_ + 2 * jp);
        unsigned hi, lo;
        bfsplit(v.x, v.y, hi, lo);
        w2h[e * W2_STR + jp] = hi;
        w2l[e * W2_STR + jp] = lo;
    }
    __syncthreads();

    for (int tt = 0; tt < TPB_; ++tt) {
        const int tile = bx * TPB_ + tt;
        const u64* q2 = g_q2 + ((size_t)b * S_ + tile * PT_ + t0) * 16;

        // ---- load q A-fragments (hi,lo) straight from gmem ----
        unsigned qah[2][4], qal[2][4];
#pragma unroll
        for (int kcq = 0; kcq < 2; ++kcq) {
            const int k8 = kcq * 8;
            u64 v0 = q2[g * 16 + k8 + c];
            u64 v1 = q2[(g + 8) * 16 + k8 + c];
            u64 v2 = q2[g * 16 + k8 + c + 4];
            u64 v3 = q2[(g + 8) * 16 + k8 + c + 4];
            qah[kcq][0] = (unsigned)v0; qal[kcq][0] = (unsigned)(v0 >> 32);
            qah[kcq][1] = (unsigned)v1; qal[kcq][1] = (unsigned)(v1 >> 32);
            qah[kcq][2] = (unsigned)v2; qal[kcq][2] = (unsigned)(v2 >> 32);
            qah[kcq][3] = (unsigned)v3; qal[kcq][3] = (unsigned)(v3 >> 32);
        }

        // ---- interleaved GEMM1/GEMM2 per k16-chunk of GEMM2 ----
        float oa[4][4];
#pragma unroll
        for (int en = 0; en < 4; ++en) {
            float blo = b2s[en * 8 + 2 * c], bhi = b2s[en * 8 + 2 * c + 1];
            oa[en][0] = blo; oa[en][1] = bhi; oa[en][2] = blo; oa[en][3] = bhi;
        }
#pragma unroll
        for (int kc = 0; kc < 4; ++kc) {
            float hp[2][4];
#pragma unroll
            for (int i = 0; i < 2; ++i) {
                const int jn = 2 * kc + i;
                float blo = b1s[jn * 8 + 2 * c], bhi = b1s[jn * 8 + 2 * c + 1];
                hp[i][0] = blo; hp[i][1] = bhi; hp[i][2] = blo; hp[i][3] = bhi;
#pragma unroll
                for (int kcq = 0; kcq < 2; ++kcq) {
                    const int jr = jn * 8 + g, k8 = kcq * 8;
                    mma_bf3(hp[i], qah[kcq], qal[kcq],
                            w1h[jr * W1_STR + k8 + c], w1h[jr * W1_STR + k8 + c + 4],
                            w1l[jr * W1_STR + k8 + c], w1l[jr * W1_STR + k8 + c + 4]);
                }
            }
            unsigned ah[4], al[4];
            bfsplit(silu_f(hp[0][0]), silu_f(hp[0][1]), ah[0], al[0]);
            bfsplit(silu_f(hp[0][2]), silu_f(hp[0][3]), ah[1], al[1]);
            bfsplit(silu_f(hp[1][0]), silu_f(hp[1][1]), ah[2], al[2]);
            bfsplit(silu_f(hp[1][2]), silu_f(hp[1][3]), ah[3], al[3]);
            const int k8 = kc * 8;
#pragma unroll
            for (int en = 0; en < 4; ++en) {
                const int er = en * 8 + g;
                mma_bf3(oa[en], ah, al,
                        w2h[er * W2_STR + k8 + c], w2h[er * W2_STR + k8 + c + 4],
                        w2l[er * W2_STR + k8 + c], w2l[er * W2_STR + k8 + c + 4]);
            }
        }
        float* ob = out + ((size_t)b * S_ + tile * PT_ + t0) * E_;
#pragma unroll
        for (int en = 0; en < 4; ++en) {
            const int e2 = en * 8 + 2 * c;
            *reinterpret_cast<float2*>(ob + g * E_ + e2) =
                make_float2(oa[en][0], oa[en][1]);
            *reinterpret_cast<float2*>(ob + (g + 8) * E_ + e2) =
                make_float2(oa[en][2], oa[en][3]);
        }
    }
}

extern "C" void kernel_launch(void* const* d_in, const int* in_sizes, int n_in,
                              void* d_out, int out_size) {
    const float* x  = (const float*)d_in[0];
    const float* Qw = (const float*)d_in[1];
    const float* W1 = (const float*)d_in[2];
    const float* b1 = (const float*)d_in[3];
    const float* W2 = (const float*)d_in[4];
    const float* b2 = (const float*)d_in[5];
    float* out = (float*)d_out;

    k_passA<<<dim3(NBA_, B_), 256>>>(x, Qw);
    k_passB<<<dim3(NBB_, B_), 256>>>(W1, b1, W2, b2, out);
}

// round 17
// speedup vs baseline: 1.2874x; 1.2874x over previous
#include <cuda_runtime.h>

#define B_ 64
#define S_ 8192
#define E_ 32
#define H_ 64
#define PT_ 128
#define PTILES_ (S_ / PT_)      // 64
#define TPA_ 4
#define NBA_ (PTILES_ / TPA_)   // 16
#define TPB_ 4
#define NBB_ (PTILES_ / TPB_)   // 16

// strides in 4-byte units (bank patterns verified R11/R14)
#define QTB_STR 20  // Qt bf16 [f=32][epair=16] u32 (pass A only)
#define W1_STR 20   // W1bf [j=64][epair=16] u32
#define W2_STR 36   // W2bf [e=32][jpair=32] u32
#define HS_STR 36   // hs [t=128][jpair=32] u32
// pass-B dynamic smem offsets (u32 units)
#define W1H_OFF 0
#define W1L_OFF (W1H_OFF + H_ * W1_STR)      // 1280
#define W2H_OFF (W1L_OFF + H_ * W1_STR)      // 2560
#define W2L_OFF (W2H_OFF + E_ * W2_STR)      // 3712
#define HSH_OFF (W2L_OFF + E_ * W2_STR)      // 4864
#define HSL_OFF (HSH_OFF + PT_ * HS_STR)     // 9472
#define B1S_OFF (HSL_OFF + PT_ * HS_STR)     // 14080
#define B2S_OFF (B1S_OFF + H_)
#define RSQ_OFF (B2S_OFF + E_)
#define SMB_U32 (RSQ_OFF + E_)               // 14208 -> 56832 B dynamic

typedef unsigned long long u64;

// q stored as packed (hi,lo) bf16x2 u64, layout [b*S + t][16 pair-cols].
__device__ static u64 g_q2[(size_t)B_ * S_ * 16];
__device__ static float g_part[B_ * NBA_ * E_];

__device__ __forceinline__ float silu_f(float v) {
    return v * __fdividef(1.0f, 1.0f + __expf(-v));
}
__device__ __forceinline__ void mma_bf16(float* d, const unsigned* a,
                                         unsigned b0, unsigned b1) {
    asm("mma.sync.aligned.m16n8k16.row.col.f32.bf16.bf16.f32 "
        "{%0,%1,%2,%3},{%4,%5,%6,%7},{%8,%9},{%0,%1,%2,%3};"
        : "+f"(d[0]), "+f"(d[1]), "+f"(d[2]), "+f"(d[3])
        : "r"(a[0]), "r"(a[1]), "r"(a[2]), "r"(a[3]), "r"(b0), "r"(b1));
}
__device__ __forceinline__ void mma_bf3(float* d, const unsigned* ah, const unsigned* al,
                                        unsigned bh0, unsigned bh1,
                                        unsigned bl0, unsigned bl1) {
    mma_bf16(d, ah, bh0, bh1);
    mma_bf16(d, ah, bl0, bl1);
    mma_bf16(d, al, bh0, bh1);
}
__device__ __forceinline__ unsigned bf2pack(float lo, float hi) {
    unsigned r; asm("cvt.rn.bf16x2.f32 %0, %1, %2;" : "=r"(r) : "f"(hi), "f"(lo));
    return r;
}
__device__ __forceinline__ void bfsplit(float v0, float v1, unsigned& hi, unsigned& lo) {
    hi = bf2pack(v0, v1);
    float h0 = __uint_as_float(hi << 16);
    float h1 = __uint_as_float(hi & 0xFFFF0000u);
    lo = bf2pack(v0 - h0, v1 - h1);
}

// ---------------- Pass A: q = silu(x @ Qw^T); store split-q; sumsq (R15 verbatim) ----
__global__ __launch_bounds__(256) void k_passA(const float* __restrict__ x,
                                               const float* __restrict__ Qw) {
    __shared__ __align__(16) unsigned QtbH[E_ * QTB_STR], QtbL[E_ * QTB_STR];
    __shared__ float ssA[8][E_];
    const int b = blockIdx.y, bx = blockIdx.x, tid = threadIdx.x;
    const int lane = tid & 31, w = tid >> 5;
    const int g = lane >> 2, c = lane & 3;
    const int t0 = w * 16;

    for (int i = tid; i < E_ * (E_ / 2); i += 256) {
        int f = i >> 4, ep = i & 15;
        float2 v = *reinterpret_cast<const float2*>(Qw + f * E_ + 2 * ep);
        unsigned hi, lo;
        bfsplit(v.x, v.y, hi, lo);
        QtbH[f * QTB_STR + ep] = hi;
        QtbL[f * QTB_STR + ep] = lo;
    }
    __syncthreads();

    float ss[4][2];
#pragma unroll
    for (int fn = 0; fn < 4; ++fn) ss[fn][0] = ss[fn][1] = 0.f;

    for (int tt = 0; tt < TPA_; ++tt) {
        const int tile = bx * TPA_ + tt;
        const float2* xw2 = reinterpret_cast<const float2*>(
            x + ((size_t)b * S_ + tile * PT_ + t0) * E_);

        float qa[4][4];
#pragma unroll
        for (int fn = 0; fn < 4; ++fn)
#pragma unroll
            for (int i = 0; i < 4; ++i) qa[fn][i] = 0.f;
#pragma unroll
        for (int kc = 0; kc < 2; ++kc) {
            const int p0 = 8 * kc;
            float2 v0 = xw2[g * 16 + p0 + c];
            float2 v1 = xw2[(g + 8) * 16 + p0 + c];
            float2 v2 = xw2[g * 16 + p0 + c + 4];
            float2 v3 = xw2[(g + 8) * 16 + p0 + c + 4];
            unsigned ah[4], al[4];
            bfsplit(v0.x, v0.y, ah[0], al[0]);
            bfsplit(v1.x, v1.y, ah[1], al[1]);
            bfsplit(v2.x, v2.y, ah[2], al[2]);
            bfsplit(v3.x, v3.y, ah[3], al[3]);
            const int k8 = kc * 8;
#pragma unroll
            for (int fn = 0; fn < 4; ++fn) {
                const int fr = fn * 8 + g;
                mma_bf3(qa[fn], ah, al,
                        QtbH[fr * QTB_STR + k8 + c], QtbH[fr * QTB_STR + k8 + c + 4],
                        QtbL[fr * QTB_STR + k8 + c], QtbL[fr * QTB_STR + k8 + c + 4]);
            }
        }

        u64* q2 = g_q2 + ((size_t)b * S_ + tile * PT_ + t0) * 16;
#pragma unroll
        for (int fn = 0; fn < 4; ++fn) {
            float s0 = silu_f(qa[fn][0]), s1 = silu_f(qa[fn][1]);
            float s2 = silu_f(qa[fn][2]), s3 = silu_f(qa[fn][3]);
            ss[fn][0] += s0 * s0 + s2 * s2;
            ss[fn][1] += s1 * s1 + s3 * s3;
            unsigned h0, l0, h2, l2;
            bfsplit(s0, s1, h0, l0);
            bfsplit(s2, s3, h2, l2);
            q2[g * 16 + fn * 4 + c]       = (u64)h0 | ((u64)l0 << 32);
            q2[(g + 8) * 16 + fn * 4 + c] = (u64)h2 | ((u64)l2 << 32);
        }
    }

#pragma unroll
    for (int m = 4; m <= 16; m <<= 1)
#pragma unroll
        for (int fn = 0; fn < 4; ++fn) {
            ss[fn][0] += __shfl_xor_sync(0xffffffffu, ss[fn][0], m);
            ss[fn][1] += __shfl_xor_sync(0xffffffffu, ss[fn][1], m);
        }
    if (lane < 4) {
#pragma unroll
        for (int fn = 0; fn < 4; ++fn) {
            ssA[w][fn * 8 + 2 * lane]     = ss[fn][0];
            ssA[w][fn * 8 + 2 * lane + 1] = ss[fn][1];
        }
    }
    __syncthreads();
    if (tid < E_) {
        float s = 0.f;
#pragma unroll
        for (int k = 0; k < 8; ++k) s += ssA[k][tid];
        g_part[(b * NBA_ + bx) * E_ + tid] = s;
    }
}

// ---- Pass B: q frags from gmem -> GEMM1 -> hs staging -> GEMM2 (dynamic smem) ----
__global__ __launch_bounds__(256) void k_passB(const float* __restrict__ W1,
                                               const float* __restrict__ b1,
                                               const float* __restrict__ W2,
                                               const float* __restrict__ b2,
                                               float* __restrict__ out) {
    extern __shared__ __align__(16) unsigned smu[];
    unsigned* w1h = smu + W1H_OFF;
    unsigned* w1l = smu + W1L_OFF;
    unsigned* w2h = smu + W2H_OFF;
    unsigned* w2l = smu + W2L_OFF;
    unsigned* hsh = smu + HSH_OFF;
    unsigned* hsl = smu + HSL_OFF;
    float* b1s = reinterpret_cast<float*>(smu + B1S_OFF);
    float* b2s = reinterpret_cast<float*>(smu + B2S_OFF);
    float* rsq = reinterpret_cast<float*>(smu + RSQ_OFF);

    const int b = blockIdx.y, bx = blockIdx.x, tid = threadIdx.x;
    const int lane = tid & 31, w = tid >> 5;
    const int g = lane >> 2, c = lane & 3;
    const int t0 = w * 16;

    if (tid < E_) {
        float s = 0.f;
#pragma unroll
        for (int k = 0; k < NBA_; ++k) s += g_part[(b * NBA_ + k) * E_ + tid];
        rsq[tid] = 1.0f / fmaxf(sqrtf(s), 1e-12f);
        b2s[tid] = b2[b * E_ + tid];
    }
    if (tid < H_) b1s[tid] = b1[b * H_ + tid];
    __syncthreads();

    const size_t wbase = (size_t)b * H_ * E_;
    for (int i = tid; i < H_ * (E_ / 2); i += 256) {
        int j = i >> 4, ep = i & 15;
        float2 v = *reinterpret_cast<const float2*>(W1 + wbase + j * E_ + 2 * ep);
        unsigned hi, lo;
        bfsplit(v.x * rsq[2 * ep], v.y * rsq[2 * ep + 1], hi, lo);
        w1h[j * W1_STR + ep] = hi;
        w1l[j * W1_STR + ep] = lo;
    }
    for (int i = tid; i < E_ * (H_ / 2); i += 256) {
        int e = i >> 5, jp = i & 31;
        float2 v = *reinterpret_cast<const float2*>(W2 + wbase + e * H_ + 2 * jp);
        unsigned hi, lo;
        bfsplit(v.x, v.y, hi, lo);
        w2h[e * W2_STR + jp] = hi;
        w2l[e * W2_STR + jp] = lo;
    }
    __syncthreads();

    for (int tt = 0; tt < TPB_; ++tt) {
        const int tile = bx * TPB_ + tt;
        const u64* q2 = g_q2 + ((size_t)b * S_ + tile * PT_ + t0) * 16;

        // ---- q A-fragments straight from gmem (coalesced LDG.64) ----
        unsigned qah[2][4], qal[2][4];
#pragma unroll
        for (int kcq = 0; kcq < 2; ++kcq) {
            const int k8 = kcq * 8;
            u64 v0 = q2[g * 16 + k8 + c];
            u64 v1 = q2[(g + 8) * 16 + k8 + c];
            u64 v2 = q2[g * 16 + k8 + c + 4];
            u64 v3 = q2[(g + 8) * 16 + k8 + c + 4];
            qah[kcq][0] = (unsigned)v0; qal[kcq][0] = (unsigned)(v0 >> 32);
            qah[kcq][1] = (unsigned)v1; qal[kcq][1] = (unsigned)(v1 >> 32);
            qah[kcq][2] = (unsigned)v2; qal[kcq][2] = (unsigned)(v2 >> 32);
            qah[kcq][3] = (unsigned)v3; qal[kcq][3] = (unsigned)(v3 >> 32);
        }

        // ---- GEMM1 (bf16 3-term), A from registers ----
        float ha[8][4];
#pragma unroll
        for (int jn = 0; jn < 8; ++jn) {
            float blo = b1s[jn * 8 + 2 * c], bhi = b1s[jn * 8 + 2 * c + 1];
            ha[jn][0] = blo; ha[jn][1] = bhi; ha[jn][2] = blo; ha[jn][3] = bhi;
        }
#pragma unroll
        for (int kcq = 0; kcq < 2; ++kcq) {
            const int k8 = kcq * 8;
#pragma unroll
            for (int jn = 0; jn < 8; ++jn) {
                const int jr = jn * 8 + g;
                mma_bf3(ha[jn], qah[kcq], qal[kcq],
                        w1h[jr * W1_STR + k8 + c], w1h[jr * W1_STR + k8 + c + 4],
                        w1l[jr * W1_STR + k8 + c], w1l[jr * W1_STR + k8 + c + 4]);
            }
        }

        // ---- silu + pack ha into hs staging (warp-local rows) ----
#pragma unroll
        for (int jn = 0; jn < 8; ++jn) {
            const int col = jn * 4 + c;
            unsigned hi, lo;
            bfsplit(silu_f(ha[jn][0]), silu_f(ha[jn][1]), hi, lo);
            hsh[(t0 + g) * HS_STR + col] = hi;
            hsl[(t0 + g) * HS_STR + col] = lo;
            bfsplit(silu_f(ha[jn][2]), silu_f(ha[jn][3]), hi, lo);
            hsh[(t0 + g + 8) * HS_STR + col] = hi;
            hsl[(t0 + g + 8) * HS_STR + col] = lo;
        }
        __syncwarp();

        // ---- GEMM2 (bf16 3-term), A from hs ----
        float oa[4][4];
#pragma unroll
        for (int en = 0; en < 4; ++en) {
            float blo = b2s[en * 8 + 2 * c], bhi = b2s[en * 8 + 2 * c + 1];
            oa[en][0] = blo; oa[en][1] = bhi; oa[en][2] = blo; oa[en][3] = bhi;
        }
#pragma unroll
        for (int kc = 0; kc < 4; ++kc) {
            const int k8 = kc * 8;
            unsigned ah[4] = {hsh[(t0 + g) * HS_STR + k8 + c],
                              hsh[(t0 + g + 8) * HS_STR + k8 + c],
                              hsh[(t0 + g) * HS_STR + k8 + c + 4],
                              hsh[(t0 + g + 8) * HS_STR + k8 + c + 4]};
            unsigned al[4] = {hsl[(t0 + g) * HS_STR + k8 + c],
                              hsl[(t0 + g + 8) * HS_STR + k8 + c],
                              hsl[(t0 + g) * HS_STR + k8 + c + 4],
                              hsl[(t0 + g + 8) * HS_STR + k8 + c + 4]};
#pragma unroll
            for (int en = 0; en < 4; ++en) {
                const int er = en * 8 + g;
                mma_bf3(oa[en], ah, al,
                        w2h[er * W2_STR + k8 + c], w2h[er * W2_STR + k8 + c + 4],
                        w2l[er * W2_STR + k8 + c], w2l[er * W2_STR + k8 + c + 4]);
            }
        }
        float* ob = out + ((size_t)b * S_ + tile * PT_ + t0) * E_;
#pragma unroll
        for (int en = 0; en < 4; ++en) {
            const int e2 = en * 8 + 2 * c;
            *reinterpret_cast<float2*>(ob + g * E_ + e2) =
                make_float2(oa[en][0], oa[en][1]);
            *reinterpret_cast<float2*>(ob + (g + 8) * E_ + e2) =
                make_float2(oa[en][2], oa[en][3]);
        }
        __syncwarp();
    }
}

extern "C" void kernel_launch(void* const* d_in, const int* in_sizes, int n_in,
                              void* d_out, int out_size) {
    const float* x  = (const float*)d_in[0];
    const float* Qw = (const float*)d_in[1];
    const float* W1 = (const float*)d_in[2];
    const float* b1 = (const float*)d_in[3];
    const float* W2 = (const float*)d_in[4];
    const float* b2 = (const float*)d_in[5];
    float* out = (float*)d_out;

    const int smemB = SMB_U32 * sizeof(unsigned);  // 56,832 B dynamic
    cudaFuncSetAttribute(k_passB, cudaFuncAttributeMaxDynamicSharedMemorySize, smemB);

    k_passA<<<dim3(NBA_, B_), 256>>>(x, Qw);
    k_passB<<<dim3(NBB_, B_), 256, smemB>>>(W1, b1, W2, b2, out);
}